// round 17
// baseline (speedup 1.0000x reference)
#include <cuda_runtime.h>

#define Hdim 128
#define PREP_BLOCKS 32
#define MAIN_BLOCKS 888
#define MAIN_THREADS 256
#define WARPS_PB (MAIN_THREADS / 32)
#define NWARP (MAIN_BLOCKS * WARPS_PB)

// scratch (no allocations allowed)
__device__ float g_u_part[PREP_BLOCKS][Hdim];
__device__ float g_c_part[PREP_BLOCKS];
__device__ double g_sum;
__device__ unsigned long long g_maxkey;
__device__ unsigned g_count;

struct f8 { float a0,a1,a2,a3,a4,a5,a6,a7; };

__device__ __forceinline__ f8 ldg8(const float* __restrict__ p) {
    f8 v;
    asm("ld.global.nc.v8.b32 {%0,%1,%2,%3,%4,%5,%6,%7}, [%8];"
        : "=f"(v.a0), "=f"(v.a1), "=f"(v.a2), "=f"(v.a3),
          "=f"(v.a4), "=f"(v.a5), "=f"(v.a6), "=f"(v.a7)
        : "l"(p));
    return v;
}

// ---------------------------------------------------------------------------
// K1 (prep): 32 blocks x 128 threads. Triggers PDL completion when done.
// ---------------------------------------------------------------------------
__global__ void __launch_bounds__(128) k_prep(const float* __restrict__ feat,
                                              const float* __restrict__ W1,
                                              const float* __restrict__ b1,
                                              const float* __restrict__ W2,
                                              const float* __restrict__ b2,
                                              const int*   __restrict__ prev)
{
    __shared__ float sphi[16];

    const int lane = threadIdx.x & 31;
    const int warp = threadIdx.x >> 5;
    const int j0   = blockIdx.x * 16;
    const int p    = prev[0];

    const float4 x = ((const float4*)(feat + (size_t)p * Hdim))[lane];

#pragma unroll
    for (int jj = 0; jj < 4; jj++) {
        const int j = j0 + warp * 4 + jj;
        const float4 w = ((const float4*)(W1 + (size_t)j * Hdim))[lane];
        float d = fmaf(w.x, x.x, fmaf(w.y, x.y, fmaf(w.z, x.z, w.w * x.w)));
        d += __shfl_xor_sync(0xffffffffu, d, 16);
        d += __shfl_xor_sync(0xffffffffu, d, 8);
        d += __shfl_xor_sync(0xffffffffu, d, 4);
        d += __shfl_xor_sync(0xffffffffu, d, 2);
        d += __shfl_xor_sync(0xffffffffu, d, 1);
        if (lane == 0) sphi[warp * 4 + jj] = d + b1[j];
    }
    __syncthreads();

    const int h = threadIdx.x;
    float acc = 0.0f;
#pragma unroll
    for (int jj = 0; jj < 16; jj++) {
        acc = fmaf(sphi[jj], W2[(size_t)(j0 + jj) * Hdim + h], acc);
    }
    g_u_part[blockIdx.x][h] = acc;

    if (threadIdx.x == 0) {
        float cp = 0.0f;
#pragma unroll
        for (int jj = 0; jj < 16; jj++) cp = fmaf(sphi[jj], b2[j0 + jj], cp);
        g_c_part[blockIdx.x] = cp;
        if (blockIdx.x == 0) { g_sum = 0.0; g_maxkey = 0ull; g_count = 0u; }
    }

#if __CUDA_ARCH__ >= 900
    cudaTriggerProgrammaticLaunchCompletion();
#endif
}

// ---------------------------------------------------------------------------
// K2 (main): 888 blocks x 256 threads, 6 blocks/SM (48 warps/SM, regs<=42).
// Light layout: 16 lanes/row (1 f8/lane), 2 rows/batch double-buffered.
// PDL secondary: first chunk's adj + first batch issued pre-sync.
// ---------------------------------------------------------------------------
__global__ void __launch_bounds__(MAIN_THREADS, 6)
k_main(const float* __restrict__ feat,
       const float* __restrict__ adj,
       float* __restrict__ out,
       int N, int out_size)
{
    __shared__ float              su[Hdim];
    __shared__ float              sc;
    __shared__ float              ssum[WARPS_PB];
    __shared__ unsigned long long skey[WARPS_PB];

    const int lane  = threadIdx.x & 31;
    const int wwarp = threadIdx.x >> 5;
    const int gwarp = blockIdx.x * WARPS_PB + wwarp;

    const int sub = lane & 15;   // f8 slot within row (0..15)
    const int grp = lane >> 4;   // which of 2 concurrent rows (0..1)

    // ---- pre-sync prefetch (independent of prep results) ----
    int base = gwarp * 32;
    float a_cur = 0.0f;
    if (base + lane < N) a_cur = __ldg(adj + base + lane);

    unsigned mask = __ballot_sync(0xffffffffu, a_cur != 0.0f);
    int m      = __popc(mask);
    int nvalid = (base < N) ? ((N - base >= 32) ? 32 : (N - base)) : 0;

    int rA = (int)__fns(mask, 0, grp + 1);
    f8 xA;
    if (base < N && rA >= 0)
        xA = ldg8(feat + (size_t)(base + rA) * Hdim + sub * 8);

#if __CUDA_ARCH__ >= 900
    cudaGridDependencySynchronize();
#endif

    // ---- reconstruct u ----
    if (threadIdx.x < Hdim) {
        float a = 0.0f;
#pragma unroll
        for (int pb = 0; pb < PREP_BLOCKS; pb++) a += g_u_part[pb][threadIdx.x];
        su[threadIdx.x] = a;
    }
    if (threadIdx.x == Hdim) {
        float a = 0.0f;
#pragma unroll
        for (int pb = 0; pb < PREP_BLOCKS; pb++) a += g_c_part[pb];
        sc = a;
    }
    __syncthreads();

    // u f8 for this lane (8 regs)
    float ureg[8];
#pragma unroll
    for (int q = 0; q < 8; q++) ureg[q] = su[sub * 8 + q];
    const float cc = sc;

    float lsum = 0.0f;
    unsigned long long lkey = 0ull;

    // ---- main loop (loop-carried mask/rA/xA; first chunk pre-loaded) ----
    while (base < N) {
        const int basen = base + NWARP * 32;
        float a_next = 0.0f;
        if (basen < N && basen + lane < N) a_next = __ldg(adj + basen + lane);

        if (lane == 0) lsum += (float)(nvalid - m);   // exp(0) per masked node

        for (int j = 0; j < m; j += 2) {
            const int rB = (int)__fns(mask, 0, j + 2 + grp + 1);
            f8 xB;
            if (rB >= 0)
                xB = ldg8(feat + (size_t)(base + rB) * Hdim + sub * 8);

            float d = 0.0f;
            if (rA >= 0) {
                float e0, e1;
                e0 = ureg[0] * xA.a0;           e1 = ureg[1] * xA.a1;
                e0 = fmaf(ureg[2], xA.a2, e0);  e1 = fmaf(ureg[3], xA.a3, e1);
                e0 = fmaf(ureg[4], xA.a4, e0);  e1 = fmaf(ureg[5], xA.a5, e1);
                e0 = fmaf(ureg[6], xA.a6, e0);  e1 = fmaf(ureg[7], xA.a7, e1);
                d = e0 + e1;
            }

            // 4-stage butterfly reduces both rows (16-lane groups)
            d += __shfl_xor_sync(0xffffffffu, d, 8);
            d += __shfl_xor_sync(0xffffffffu, d, 4);
            d += __shfl_xor_sync(0xffffffffu, d, 2);
            d += __shfl_xor_sync(0xffffffffu, d, 1);

            if (sub == 0 && rA >= 0) {
                const float s    = (d + cc) * 0.04419417382415922f; // 1/sqrt(512)
                const float attn = 10.0f * tanhf(s);
                lsum += expf(attn);
                if (attn != 0.0f) {
                    const unsigned n   = (unsigned)(base + rA);
                    const unsigned b   = __float_as_uint(attn);
                    const unsigned enc = (b & 0x80000000u) ? ~b : (b | 0x80000000u);
                    const unsigned long long key =
                        ((unsigned long long)enc << 32) |
                        (unsigned long long)(0xFFFFFFFFu - n);
                    if (key > lkey) lkey = key;
                }
            }
            rA = rB;
            xA = xB;
        }

        a_cur = a_next;
        base  = basen;
        if (base < N) {
            mask   = __ballot_sync(0xffffffffu, a_cur != 0.0f);
            m      = __popc(mask);
            nvalid = (N - base >= 32) ? 32 : (N - base);
            rA     = (int)__fns(mask, 0, grp + 1);
            if (rA >= 0)
                xA = ldg8(feat + (size_t)(base + rA) * Hdim + sub * 8);
        }
    }

    // ---- reductions + finalize ----
#pragma unroll
    for (int s = 16; s; s >>= 1) {
        lsum += __shfl_xor_sync(0xffffffffu, lsum, s);
        const unsigned long long o = __shfl_xor_sync(0xffffffffu, lkey, s);
        if (o > lkey) lkey = o;
    }

    if (lane == 0) { ssum[wwarp] = lsum; skey[wwarp] = lkey; }
    __syncthreads();

    if (threadIdx.x == 0) {
        float bs = 0.0f;
        unsigned long long bk = 0ull;
#pragma unroll
        for (int i = 0; i < WARPS_PB; i++) {
            bs += ssum[i];
            if (skey[i] > bk) bk = skey[i];
        }
        atomicAdd(&g_sum, (double)bs);
        atomicMax(&g_maxkey, bk);
        __threadfence();
        const unsigned done = atomicAdd(&g_count, 1u);
        if (done == MAIN_BLOCKS - 1u) {
            const double total = atomicAdd(&g_sum, 0.0);
            const unsigned long long k = atomicMax(&g_maxkey, 0ull);
            float pidx = 0.0f, pval = 0.0f;
            if (k != 0ull) {
                const unsigned enc = (unsigned)(k >> 32);
                const unsigned bb  = (enc & 0x80000000u) ? (enc ^ 0x80000000u) : ~enc;
                const float amax   = __uint_as_float(bb);
                const int   idx    = (int)(0xFFFFFFFFu - (unsigned)(k & 0xFFFFFFFFull));
                pidx = (float)idx;
                pval = (float)(exp((double)amax) / total);
            }
            out[0] = pidx;
            if (out_size > 1) out[1] = pval;
        }
    }
}

// ---------------------------------------------------------------------------
// inputs (metadata order): output[N,128], adj[N], W1[512,128], b1[512],
//                          W2[512,128], b2[512], prev_node (int scalar)
// ---------------------------------------------------------------------------
extern "C" void kernel_launch(void* const* d_in, const int* in_sizes, int n_in,
                              void* d_out, int out_size)
{
    const float* feat = (const float*)d_in[0];
    const float* adj  = (const float*)d_in[1];
    const float* W1   = (const float*)d_in[2];
    const float* b1   = (const float*)d_in[3];
    const float* W2   = (const float*)d_in[4];
    const float* b2   = (const float*)d_in[5];
    const int*   prev = (const int*)d_in[6];
    float* out = (float*)d_out;

    const int N = in_sizes[1];   // adj has N elements

    k_prep<<<PREP_BLOCKS, 128>>>(feat, W1, b1, W2, b2, prev);

    // PDL: k_main launches while k_prep runs; gates itself before reading
    // prep results.
    cudaLaunchConfig_t cfg = {};
    cfg.gridDim  = dim3(MAIN_BLOCKS, 1, 1);
    cfg.blockDim = dim3(MAIN_THREADS, 1, 1);
    cudaLaunchAttribute attr[1];
    attr[0].id = cudaLaunchAttributeProgrammaticStreamSerialization;
    attr[0].val.programmaticStreamSerializationAllowed = 1;
    cfg.attrs    = attr;
    cfg.numAttrs = 1;
    cudaLaunchKernelEx(&cfg, k_main, feat, adj, out, N, out_size);
}